// round 1
// baseline (speedup 1.0000x reference)
#include <cuda_runtime.h>
#include <math.h>

#define BB  16
#define NQ  256
#define NKV 256
#define DD  64

// scratch: proj_equi[b,k,c,d] = sum_e v_equi[b,k,c,e] * W_coord[d,e]
__device__ float g_proj[BB * NKV * 3 * DD];

// ---------------------------------------------------------------------------
// Kernel A: proj = v_equi @ W_coord^T    (rows = B*NKV*3 = 12288, 64-wide)
// One warp per row; lane l owns d-pair (2l, 2l+1). W_coord transposed in SMEM.
// ---------------------------------------------------------------------------
__global__ void __launch_bounds__(128) proj_kernel(const float* __restrict__ v,
                                                   const float* __restrict__ Wc) {
    __shared__ __align__(16) float Wt[64 * 66];   // Wt[e*66 + d] = Wc[d*64 + e]
    __shared__ __align__(16) float vbuf[4][64];

    int t = threadIdx.x;
    for (int i = t; i < 4096; i += 128) {
        Wt[(i & 63) * 66 + (i >> 6)] = Wc[i];
    }
    __syncthreads();

    int w = t >> 5, l = t & 31;
    const int nrows = BB * NKV * 3;
    for (int r = blockIdx.x * 4 + w; r < nrows; r += gridDim.x * 4) {
        float2 v2 = ((const float2*)(v + r * 64))[l];
        vbuf[w][2 * l] = v2.x;
        vbuf[w][2 * l + 1] = v2.y;
        __syncwarp();
        float ax = 0.f, ay = 0.f;
        #pragma unroll
        for (int e = 0; e < 64; e++) {
            float vv = vbuf[w][e];
            float2 wt = *(const float2*)(Wt + e * 66 + 2 * l);
            ax = fmaf(vv, wt.x, ax);
            ay = fmaf(vv, wt.y, ay);
        }
        float2 o = make_float2(ax, ay);
        ((float2*)(g_proj + r * 64))[l] = o;
        __syncwarp();
    }
}

// ---------------------------------------------------------------------------
// Main kernel: masked per-channel softmax over k, weighted sum with proj,
// L2-norm scaling, then @ W_attn^T.
// CTA = (b, 4 consecutive q). One warp fully owns one q; lane l owns d-pair.
// adj mask -> 256-bit bitmask in registers; ffs loop visits ONLY active k
// (skips load + exp + FMA for ~50% of k's, halving HBM traffic).
// ---------------------------------------------------------------------------
__global__ void __launch_bounds__(128) attn_kernel(const float* __restrict__ msg,
                                                   const int*   __restrict__ adjm,
                                                   const float* __restrict__ Wa,
                                                   float*       __restrict__ out) {
    __shared__ __align__(16) float Wt[64 * 65];   // Wt[e*65 + d] = Wa[d*64 + e]
    __shared__ __align__(16) float ao[12][64];    // [q_local*3 + c][e]

    int t = threadIdx.x;
    int w = t >> 5, l = t & 31;
    int b = blockIdx.x >> 6;
    int qbase = (blockIdx.x & 63) << 2;
    int q = qbase + w;

    // stage W_attn transposed (stride-65 => conflict-free both ways)
    for (int i = t; i < 4096; i += 128) {
        Wt[(i & 63) * 65 + (i >> 6)] = Wa[i];
    }

    // build 256-bit active mask for this q
    const int* arow = adjm + (b * NQ + q) * NKV;
    unsigned mask[8];
    unsigned any = 0u;
    #pragma unroll
    for (int c = 0; c < 8; c++) {
        mask[c] = __ballot_sync(0xffffffffu, arow[c * 32 + l] != 0);
        any |= mask[c];
    }
    if (!any) {   // row with no edges: mask -> 0 everywhere, i.e. all k active
        #pragma unroll
        for (int c = 0; c < 8; c++) mask[c] = 0xffffffffu;
    }

    const float2* msg2  = (const float2*)msg + (size_t)(b * NQ + q) * (NKV * 32);
    const float2* proj2 = (const float2*)g_proj + (size_t)b * (NKV * 3 * 32);

    float dnx = 0.f, dny = 0.f;        // softmax denominators
    float w2x = 0.f, w2y = 0.f;        // sum exp^2
    float a0x = 0.f, a0y = 0.f;        // sum exp * proj[c]
    float a1x = 0.f, a1y = 0.f;
    float a2x = 0.f, a2y = 0.f;

    for (int c = 0; c < 8; c++) {
        unsigned m = mask[c];
        while (m) {
            int ki = __ffs(m) - 1;
            m &= m - 1;
            int k = c * 32 + ki;
            float2 mg = msg2[k * 32 + l];
            float2 p0 = proj2[k * 96 + l];
            float2 p1 = proj2[k * 96 + 32 + l];
            float2 p2 = proj2[k * 96 + 64 + l];
            float e0 = __expf(mg.x);
            float e1 = __expf(mg.y);
            dnx += e0;                  dny += e1;
            w2x = fmaf(e0, e0, w2x);    w2y = fmaf(e1, e1, w2y);
            a0x = fmaf(e0, p0.x, a0x);  a0y = fmaf(e1, p0.y, a0y);
            a1x = fmaf(e0, p1.x, a1x);  a1y = fmaf(e1, p1.y, a1y);
            a2x = fmaf(e0, p2.x, a2x);  a2y = fmaf(e1, p2.y, a2y);
        }
    }

    // attn_out = (acc/den) * (sqrt(w2)/den) = acc * sqrt(w2) / den^2
    float sx = sqrtf(w2x) / (dnx * dnx);
    float sy = sqrtf(w2y) / (dny * dny);
    ao[w * 3 + 0][2 * l] = a0x * sx;  ao[w * 3 + 0][2 * l + 1] = a0y * sy;
    ao[w * 3 + 1][2 * l] = a1x * sx;  ao[w * 3 + 1][2 * l + 1] = a1y * sy;
    ao[w * 3 + 2][2 * l] = a2x * sx;  ao[w * 3 + 2][2 * l + 1] = a2y * sy;
    __syncthreads();

    // epilogue: out[(q,c),d] = sum_e ao[(q,c)][e] * Wa[d][e]
    // 12 (q,c) rows split over 2 thread-halves (d = t&63), 6 rows each.
    int d = t & 63;
    int half = t >> 6;
    float acc[6];
    const float* aop[6];
    #pragma unroll
    for (int j = 0; j < 6; j++) {
        acc[j] = 0.f;
        aop[j] = &ao[0][0] + (half + 2 * j) * 64;
    }
    #pragma unroll 4
    for (int e = 0; e < 64; e++) {
        float wt = Wt[e * 65 + d];
        #pragma unroll
        for (int j = 0; j < 6; j++) {
            acc[j] = fmaf(aop[j][e], wt, acc[j]);
        }
    }
    float* orow = out + ((size_t)(b * NQ + qbase) * 3) * 64;
    #pragma unroll
    for (int j = 0; j < 6; j++) {
        int jj = half + 2 * j;          // jj = q_local*3 + c
        orow[jj * 64 + d] = acc[j];
    }
}

extern "C" void kernel_launch(void* const* d_in, const int* in_sizes, int n_in,
                              void* d_out, int out_size) {
    const float* v_equi   = (const float*)d_in[0];
    const float* messages = (const float*)d_in[1];
    const int*   adj_mask = (const int*)d_in[2];
    const float* W_coord  = (const float*)d_in[3];
    const float* W_attn   = (const float*)d_in[4];
    float* out = (float*)d_out;

    proj_kernel<<<296, 128>>>(v_equi, W_coord);
    attn_kernel<<<BB * (NQ / 4), 128>>>(messages, adj_mask, W_attn, out);
}

// round 2
// speedup vs baseline: 1.2799x; 1.2799x over previous
#include <cuda_runtime.h>
#include <math.h>

#define BB  16
#define NQ  256
#define NKV 256
#define DD  64

// scratch: proj_equi[b,k,c,d] = sum_e v_equi[b,k,c,e] * W_coord[d,e]
__device__ float g_proj[BB * NKV * 3 * DD];

// ---------------------------------------------------------------------------
// Kernel A: proj = v_equi @ W_coord^T  (12288 rows of 64)
// One warp per GROUP of 4 rows: Wt read once per e, 8 FMAs against it.
// vbuf read via float4 broadcast (1 LDS.128 per 4 e's per row).
// ---------------------------------------------------------------------------
__global__ void __launch_bounds__(128) proj_kernel(const float* __restrict__ v,
                                                   const float* __restrict__ Wc) {
    __shared__ __align__(16) float Wt[64 * 66];      // Wt[e*66 + d] = Wc[d*64 + e]
    __shared__ __align__(16) float vbuf[4][4][64];   // [warp][row][e]

    int t = threadIdx.x;
    for (int i = t; i < 4096; i += 128) {
        Wt[(i & 63) * 66 + (i >> 6)] = Wc[i];
    }
    __syncthreads();

    int w = t >> 5, l = t & 31;
    int r0 = (blockIdx.x * 4 + w) * 4;               // 768 CTAs * 4 warps * 4 rows = 12288

    #pragma unroll
    for (int r = 0; r < 4; r++) {
        float2 tv = ((const float2*)(v + (size_t)(r0 + r) * 64))[l];
        vbuf[w][r][2 * l]     = tv.x;
        vbuf[w][r][2 * l + 1] = tv.y;
    }
    __syncwarp();

    float ax[4] = {0.f, 0.f, 0.f, 0.f};
    float ay[4] = {0.f, 0.f, 0.f, 0.f};
    #pragma unroll
    for (int e4 = 0; e4 < 16; e4++) {
        float4 vv[4];
        #pragma unroll
        for (int r = 0; r < 4; r++) vv[r] = *(const float4*)&vbuf[w][r][e4 * 4];
        #pragma unroll
        for (int i = 0; i < 4; i++) {
            float2 wt = *(const float2*)(Wt + (e4 * 4 + i) * 66 + 2 * l);
            #pragma unroll
            for (int r = 0; r < 4; r++) {
                float vr = ((const float*)&vv[r])[i];
                ax[r] = fmaf(vr, wt.x, ax[r]);
                ay[r] = fmaf(vr, wt.y, ay[r]);
            }
        }
    }
    #pragma unroll
    for (int r = 0; r < 4; r++) {
        ((float2*)(g_proj + (size_t)(r0 + r) * 64))[l] = make_float2(ax[r], ay[r]);
    }
}

// ---------------------------------------------------------------------------
// Main kernel. CTA = (b, 4 q). Warp owns one q; lane l owns d-pair (2l,2l+1).
// Active-k set compacted to a smem index list (breaks the ffs dependency
// chain), then consumed in batches of 4 -> 16 LDG.64 in flight per warp.
// ---------------------------------------------------------------------------
__global__ void __launch_bounds__(128) attn_kernel(const float* __restrict__ msg,
                                                   const int*   __restrict__ adjm,
                                                   const float* __restrict__ Wa,
                                                   float*       __restrict__ out) {
    __shared__ __align__(16) float Wt[64 * 65];      // Wt[e*65 + d] = Wa[d*64 + e]
    __shared__ __align__(16) float ao[12][64];       // [q_local*3 + c][e]
    __shared__ short klist[4][NKV + 4];

    int t = threadIdx.x;
    int w = t >> 5, l = t & 31;
    int b = blockIdx.x >> 6;
    int qbase = (blockIdx.x & 63) << 2;
    int q = qbase + w;

    for (int i = t; i < 4096; i += 128) {
        Wt[(i & 63) * 65 + (i >> 6)] = Wa[i];
    }

    // build mask + compact active-k list
    const int* arow = adjm + (b * NQ + q) * NKV;
    unsigned mask[8];
    unsigned any = 0u;
    #pragma unroll
    for (int c = 0; c < 8; c++) {
        mask[c] = __ballot_sync(0xffffffffu, arow[c * 32 + l] != 0);
        any |= mask[c];
    }
    if (!any) {
        #pragma unroll
        for (int c = 0; c < 8; c++) mask[c] = 0xffffffffu;
    }
    int cnt = 0;
    #pragma unroll
    for (int c = 0; c < 8; c++) {
        unsigned m = mask[c];
        if ((m >> l) & 1u) {
            klist[w][cnt + __popc(m & ((1u << l) - 1u))] = (short)(c * 32 + l);
        }
        cnt += __popc(m);
    }
    __syncwarp();
    if (l < 4) klist[w][cnt + l] = klist[w][cnt - 1];   // pad (cnt >= 1 always)
    __syncwarp();

    const float2* msg2  = (const float2*)msg + (size_t)(b * NQ + q) * (NKV * 32);
    const float2* proj2 = (const float2*)g_proj + (size_t)b * (NKV * 3 * 32);

    float dnx = 0.f, dny = 0.f;
    float w2x = 0.f, w2y = 0.f;
    float a0x = 0.f, a0y = 0.f;
    float a1x = 0.f, a1y = 0.f;
    float a2x = 0.f, a2y = 0.f;

    for (int j = 0; j < cnt; j += 4) {
        int k0 = klist[w][j + 0];
        int k1 = klist[w][j + 1];
        int k2 = klist[w][j + 2];
        int k3 = klist[w][j + 3];
        // issue all 16 loads before consuming
        float2 mg0 = msg2[k0 * 32 + l];
        float2 mg1 = msg2[k1 * 32 + l];
        float2 mg2 = msg2[k2 * 32 + l];
        float2 mg3 = msg2[k3 * 32 + l];
        float2 p00 = proj2[k0 * 96 + l], p01 = proj2[k0 * 96 + 32 + l], p02 = proj2[k0 * 96 + 64 + l];
        float2 p10 = proj2[k1 * 96 + l], p11 = proj2[k1 * 96 + 32 + l], p12 = proj2[k1 * 96 + 64 + l];
        float2 p20 = proj2[k2 * 96 + l], p21 = proj2[k2 * 96 + 32 + l], p22 = proj2[k2 * 96 + 64 + l];
        float2 p30 = proj2[k3 * 96 + l], p31 = proj2[k3 * 96 + 32 + l], p32 = proj2[k3 * 96 + 64 + l];

        float f1 = (j + 1 < cnt) ? 1.f : 0.f;
        float f2 = (j + 2 < cnt) ? 1.f : 0.f;
        float f3 = (j + 3 < cnt) ? 1.f : 0.f;

        float e0x = __expf(mg0.x),      e0y = __expf(mg0.y);
        float e1x = __expf(mg1.x) * f1, e1y = __expf(mg1.y) * f1;
        float e2x = __expf(mg2.x) * f2, e2y = __expf(mg2.y) * f2;
        float e3x = __expf(mg3.x) * f3, e3y = __expf(mg3.y) * f3;

        dnx += e0x + e1x + e2x + e3x;
        dny += e0y + e1y + e2y + e3y;
        w2x = fmaf(e0x, e0x, fmaf(e1x, e1x, fmaf(e2x, e2x, fmaf(e3x, e3x, w2x))));
        w2y = fmaf(e0y, e0y, fmaf(e1y, e1y, fmaf(e2y, e2y, fmaf(e3y, e3y, w2y))));
        a0x = fmaf(e0x, p00.x, fmaf(e1x, p10.x, fmaf(e2x, p20.x, fmaf(e3x, p30.x, a0x))));
        a0y = fmaf(e0y, p00.y, fmaf(e1y, p10.y, fmaf(e2y, p20.y, fmaf(e3y, p30.y, a0y))));
        a1x = fmaf(e0x, p01.x, fmaf(e1x, p11.x, fmaf(e2x, p21.x, fmaf(e3x, p31.x, a1x))));
        a1y = fmaf(e0y, p01.y, fmaf(e1y, p11.y, fmaf(e2y, p21.y, fmaf(e3y, p31.y, a1y))));
        a2x = fmaf(e0x, p02.x, fmaf(e1x, p12.x, fmaf(e2x, p22.x, fmaf(e3x, p32.x, a2x))));
        a2y = fmaf(e0y, p02.y, fmaf(e1y, p12.y, fmaf(e2y, p22.y, fmaf(e3y, p32.y, a2y))));
    }

    // attn_out = acc * sqrt(w2) / den^2
    float sx = sqrtf(w2x) / (dnx * dnx);
    float sy = sqrtf(w2y) / (dny * dny);
    ao[w * 3 + 0][2 * l] = a0x * sx;  ao[w * 3 + 0][2 * l + 1] = a0y * sy;
    ao[w * 3 + 1][2 * l] = a1x * sx;  ao[w * 3 + 1][2 * l + 1] = a1y * sy;
    ao[w * 3 + 2][2 * l] = a2x * sx;  ao[w * 3 + 2][2 * l + 1] = a2y * sy;
    __syncthreads();

    // epilogue: out[(q,c),d] = sum_e ao[(q,c)][e] * Wa[d][e]
    int d = t & 63;
    int half = t >> 6;
    float acc[6];
    const float* aop[6];
    #pragma unroll
    for (int jj = 0; jj < 6; jj++) {
        acc[jj] = 0.f;
        aop[jj] = &ao[0][0] + (half + 2 * jj) * 64;
    }
    #pragma unroll 4
    for (int e = 0; e < 64; e++) {
        float wt = Wt[e * 65 + d];
        #pragma unroll
        for (int jj = 0; jj < 6; jj++) {
            acc[jj] = fmaf(aop[jj][e], wt, acc[jj]);
        }
    }
    float* orow = out + ((size_t)(b * NQ + qbase) * 3) * 64;
    #pragma unroll
    for (int jj = 0; jj < 6; jj++) {
        int r = half + 2 * jj;          // r = q_local*3 + c
        orow[r * 64 + d] = acc[jj];
    }
}

extern "C" void kernel_launch(void* const* d_in, const int* in_sizes, int n_in,
                              void* d_out, int out_size) {
    const float* v_equi   = (const float*)d_in[0];
    const float* messages = (const float*)d_in[1];
    const int*   adj_mask = (const int*)d_in[2];
    const float* W_coord  = (const float*)d_in[3];
    const float* W_attn   = (const float*)d_in[4];
    float* out = (float*)d_out;

    proj_kernel<<<768, 128>>>(v_equi, W_coord);
    attn_kernel<<<BB * (NQ / 4), 128>>>(messages, adj_mask, W_attn, out);
}

// round 3
// speedup vs baseline: 1.7822x; 1.3925x over previous
#include <cuda_runtime.h>
#include <math.h>

#define BB  16
#define NQ  256
#define NKV 256
#define DD  64

// scratch: proj_equi[b,k,c,d] = sum_e v_equi[b,k,c,e] * W_coord[d,e]
__device__ float g_proj[BB * NKV * 3 * DD];

// ---------------------------------------------------------------------------
// Kernel A: proj = v_equi @ W_coord^T  (12288 rows of 64)
// 2 rows per warp, grid 1536 -> ~41 warps/SM. v loads issued before the
// Wt-staging syncthreads to overlap their latency.
// ---------------------------------------------------------------------------
__global__ void __launch_bounds__(128) proj_kernel(const float* __restrict__ v,
                                                   const float* __restrict__ Wc) {
    __shared__ __align__(16) float Wt[64 * 66];      // Wt[e*66 + d] = Wc[d*64 + e]
    __shared__ __align__(16) float vbuf[4][2][64];   // [warp][row][e]

    int t = threadIdx.x;
    int w = t >> 5, l = t & 31;
    int r0 = (blockIdx.x * 4 + w) * 2;               // 1536 CTAs * 4 warps * 2 rows

    // issue gmem loads first (overlap with Wt staging)
    float2 v0 = ((const float2*)(v + (size_t)r0 * 64))[l];
    float2 v1 = ((const float2*)(v + (size_t)(r0 + 1) * 64))[l];

    for (int i = t; i < 4096; i += 128) {
        Wt[(i & 63) * 66 + (i >> 6)] = Wc[i];
    }

    vbuf[w][0][2 * l] = v0.x;  vbuf[w][0][2 * l + 1] = v0.y;
    vbuf[w][1][2 * l] = v1.x;  vbuf[w][1][2 * l + 1] = v1.y;
    __syncthreads();

    float a0x = 0.f, a0y = 0.f, a1x = 0.f, a1y = 0.f;
    #pragma unroll
    for (int e4 = 0; e4 < 16; e4++) {
        float4 va = *(const float4*)&vbuf[w][0][e4 * 4];
        float4 vb = *(const float4*)&vbuf[w][1][e4 * 4];
        #pragma unroll
        for (int i = 0; i < 4; i++) {
            float2 wt = *(const float2*)(Wt + (e4 * 4 + i) * 66 + 2 * l);
            float fa = ((const float*)&va)[i];
            float fb = ((const float*)&vb)[i];
            a0x = fmaf(fa, wt.x, a0x);
            a0y = fmaf(fa, wt.y, a0y);
            a1x = fmaf(fb, wt.x, a1x);
            a1y = fmaf(fb, wt.y, a1y);
        }
    }
    ((float2*)(g_proj + (size_t)r0 * 64))[l]       = make_float2(a0x, a0y);
    ((float2*)(g_proj + (size_t)(r0 + 1) * 64))[l] = make_float2(a1x, a1y);
}

// ---------------------------------------------------------------------------
// Main kernel. CTA = (b, 4 q). Warp owns one q; lane l owns d-pair (2l,2l+1).
// Active-k list in smem; k-loop SOFTWARE-PIPELINED (batch 2, prefetch next
// batch's 8 loads before consuming current) so loads stay in flight during
// compute instead of being drained per batch.
// ---------------------------------------------------------------------------
__global__ void __launch_bounds__(128, 8) attn_kernel(const float* __restrict__ msg,
                                                      const int*   __restrict__ adjm,
                                                      const float* __restrict__ Wa,
                                                      float*       __restrict__ out) {
    __shared__ __align__(16) float Wt[64 * 65];      // Wt[e*65 + d] = Wa[d*64 + e]
    __shared__ __align__(16) float ao[12][64];       // [q_local*3 + c][e]
    __shared__ short klist[4][NKV + 8];

    int t = threadIdx.x;
    int w = t >> 5, l = t & 31;
    int b = blockIdx.x >> 6;
    int qbase = (blockIdx.x & 63) << 2;
    int q = qbase + w;

    for (int i = t; i < 4096; i += 128) {
        Wt[(i & 63) * 65 + (i >> 6)] = Wa[i];
    }

    // build mask + compact active-k list
    const int* arow = adjm + (b * NQ + q) * NKV;
    unsigned mask[8];
    unsigned any = 0u;
    #pragma unroll
    for (int c = 0; c < 8; c++) {
        mask[c] = __ballot_sync(0xffffffffu, arow[c * 32 + l] != 0);
        any |= mask[c];
    }
    if (!any) {
        #pragma unroll
        for (int c = 0; c < 8; c++) mask[c] = 0xffffffffu;
    }
    int cnt = 0;
    #pragma unroll
    for (int c = 0; c < 8; c++) {
        unsigned m = mask[c];
        if ((m >> l) & 1u) {
            klist[w][cnt + __popc(m & ((1u << l) - 1u))] = (short)(c * 32 + l);
        }
        cnt += __popc(m);
    }
    __syncwarp();
    if (l < 6) klist[w][cnt + l] = klist[w][cnt - 1];   // pad (cnt >= 1 always)
    __syncwarp();

    const float2* msg2  = (const float2*)msg + (size_t)(b * NQ + q) * (NKV * 32);
    const float2* proj2 = (const float2*)g_proj + (size_t)b * (NKV * 3 * 32);

    float dnx = 0.f, dny = 0.f;
    float w2x = 0.f, w2y = 0.f;
    float a0x = 0.f, a0y = 0.f;
    float a1x = 0.f, a1y = 0.f;
    float a2x = 0.f, a2y = 0.f;

    // pipeline prologue: load batch 0
    int ka = klist[w][0], kb = klist[w][1];
    float2 bm0 = msg2[ka * 32 + l];
    float2 bm1 = msg2[kb * 32 + l];
    float2 bp00 = proj2[ka * 96 + l], bp01 = proj2[ka * 96 + 32 + l], bp02 = proj2[ka * 96 + 64 + l];
    float2 bp10 = proj2[kb * 96 + l], bp11 = proj2[kb * 96 + 32 + l], bp12 = proj2[kb * 96 + 64 + l];

    for (int j = 0; j < cnt; j += 2) {
        // move current stage into compute regs
        float2 m0 = bm0, m1 = bm1;
        float2 p00 = bp00, p01 = bp01, p02 = bp02;
        float2 p10 = bp10, p11 = bp11, p12 = bp12;
        // prefetch next batch (padded list keeps indices valid)
        int kn0 = klist[w][j + 2], kn1 = klist[w][j + 3];
        bm0 = msg2[kn0 * 32 + l];
        bm1 = msg2[kn1 * 32 + l];
        bp00 = proj2[kn0 * 96 + l]; bp01 = proj2[kn0 * 96 + 32 + l]; bp02 = proj2[kn0 * 96 + 64 + l];
        bp10 = proj2[kn1 * 96 + l]; bp11 = proj2[kn1 * 96 + 32 + l]; bp12 = proj2[kn1 * 96 + 64 + l];

        float f1 = (j + 1 < cnt) ? 1.f : 0.f;
        float e0x = __expf(m0.x),      e0y = __expf(m0.y);
        float e1x = __expf(m1.x) * f1, e1y = __expf(m1.y) * f1;

        dnx += e0x + e1x;
        dny += e0y + e1y;
        w2x = fmaf(e0x, e0x, fmaf(e1x, e1x, w2x));
        w2y = fmaf(e0y, e0y, fmaf(e1y, e1y, w2y));
        a0x = fmaf(e0x, p00.x, fmaf(e1x, p10.x, a0x));
        a0y = fmaf(e0y, p00.y, fmaf(e1y, p10.y, a0y));
        a1x = fmaf(e0x, p01.x, fmaf(e1x, p11.x, a1x));
        a1y = fmaf(e0y, p01.y, fmaf(e1y, p11.y, a1y));
        a2x = fmaf(e0x, p02.x, fmaf(e1x, p12.x, a2x));
        a2y = fmaf(e0y, p02.y, fmaf(e1y, p12.y, a2y));
    }

    // attn_out = acc * sqrt(w2) / den^2
    float sx = sqrtf(w2x) / (dnx * dnx);
    float sy = sqrtf(w2y) / (dny * dny);
    ao[w * 3 + 0][2 * l] = a0x * sx;  ao[w * 3 + 0][2 * l + 1] = a0y * sy;
    ao[w * 3 + 1][2 * l] = a1x * sx;  ao[w * 3 + 1][2 * l + 1] = a1y * sy;
    ao[w * 3 + 2][2 * l] = a2x * sx;  ao[w * 3 + 2][2 * l + 1] = a2y * sy;
    __syncthreads();

    // epilogue: out[(q,c),d] = sum_e ao[(q,c)][e] * Wa[d][e]
    int d = t & 63;
    int half = t >> 6;
    float acc[6];
    const float* aop[6];
    #pragma unroll
    for (int jj = 0; jj < 6; jj++) {
        acc[jj] = 0.f;
        aop[jj] = &ao[0][0] + (half + 2 * jj) * 64;
    }
    #pragma unroll 4
    for (int e = 0; e < 64; e++) {
        float wt = Wt[e * 65 + d];
        #pragma unroll
        for (int jj = 0; jj < 6; jj++) {
            acc[jj] = fmaf(aop[jj][e], wt, acc[jj]);
        }
    }
    float* orow = out + ((size_t)(b * NQ + qbase) * 3) * 64;
    #pragma unroll
    for (int jj = 0; jj < 6; jj++) {
        int r = half + 2 * jj;          // r = q_local*3 + c
        orow[r * 64 + d] = acc[jj];
    }
}

extern "C" void kernel_launch(void* const* d_in, const int* in_sizes, int n_in,
                              void* d_out, int out_size) {
    const float* v_equi   = (const float*)d_in[0];
    const float* messages = (const float*)d_in[1];
    const int*   adj_mask = (const int*)d_in[2];
    const float* W_coord  = (const float*)d_in[3];
    const float* W_attn   = (const float*)d_in[4];
    float* out = (float*)d_out;

    proj_kernel<<<1536, 128>>>(v_equi, W_coord);
    attn_kernel<<<BB * (NQ / 4), 128>>>(messages, adj_mask, W_attn, out);
}

// round 4
// speedup vs baseline: 1.8350x; 1.0297x over previous
#include <cuda_runtime.h>
#include <math.h>

#define BB  16
#define NQ  256
#define NKV 256
#define DD  64

// scratch: proj_equi[b,k,c,d] = sum_e v_equi[b,k,c,e] * W_coord[d,e]
__device__ float g_proj[BB * NKV * 3 * DD];

// ---------------------------------------------------------------------------
// Kernel A (persistent): proj = v_equi @ W_coord^T  (12288 rows of 64).
// 296 CTAs stage W once, then each warp loops over ~10 row-pairs, prefetching
// the next pair's v loads into registers while computing the current pair.
// ---------------------------------------------------------------------------
__global__ void __launch_bounds__(128) proj_kernel(const float* __restrict__ v,
                                                   const float* __restrict__ Wc) {
    __shared__ __align__(16) float Wt[64 * 66];      // Wt[e*66 + d] = Wc[d*64 + e]
    __shared__ __align__(16) float vbuf[4][2][64];   // [warp][row][e]

    int t = threadIdx.x;
    int w = t >> 5, l = t & 31;

    for (int i = t; i < 4096; i += 128) {
        Wt[(i & 63) * 66 + (i >> 6)] = Wc[i];
    }
    __syncthreads();

    const int NPAIR = (BB * NKV * 3) / 2;            // 6144 row-pairs
    const int STRIDE = 296 * 4;                      // warps in grid
    int p = blockIdx.x * 4 + w;
    if (p >= NPAIR) return;

    float2 v0 = ((const float2*)(v + (size_t)(2 * p) * 64))[l];
    float2 v1 = ((const float2*)(v + (size_t)(2 * p + 1) * 64))[l];

    for (; p < NPAIR; p += STRIDE) {
        vbuf[w][0][2 * l] = v0.x;  vbuf[w][0][2 * l + 1] = v0.y;
        vbuf[w][1][2 * l] = v1.x;  vbuf[w][1][2 * l + 1] = v1.y;
        __syncwarp();

        // prefetch next pair
        int pn = p + STRIDE;
        if (pn < NPAIR) {
            v0 = ((const float2*)(v + (size_t)(2 * pn) * 64))[l];
            v1 = ((const float2*)(v + (size_t)(2 * pn + 1) * 64))[l];
        }

        float a0x = 0.f, a0y = 0.f, a1x = 0.f, a1y = 0.f;
        #pragma unroll
        for (int e4 = 0; e4 < 16; e4++) {
            float4 va = *(const float4*)&vbuf[w][0][e4 * 4];
            float4 vb = *(const float4*)&vbuf[w][1][e4 * 4];
            #pragma unroll
            for (int i = 0; i < 4; i++) {
                float2 wt = *(const float2*)(Wt + (e4 * 4 + i) * 66 + 2 * l);
                float fa = ((const float*)&va)[i];
                float fb = ((const float*)&vb)[i];
                a0x = fmaf(fa, wt.x, a0x);
                a0y = fmaf(fa, wt.y, a0y);
                a1x = fmaf(fb, wt.x, a1x);
                a1y = fmaf(fb, wt.y, a1y);
            }
        }
        ((float2*)(g_proj + (size_t)(2 * p) * 64))[l]     = make_float2(a0x, a0y);
        ((float2*)(g_proj + (size_t)(2 * p + 1) * 64))[l] = make_float2(a1x, a1y);
        __syncwarp();
    }
}

// ---------------------------------------------------------------------------
// Main kernel. CTA = (b, 4 q). Warp owns one q. HALF-WARP-K layout:
// lane l: li = l&15 owns d-quad [4*li, 4*li+4); h = l>>4 selects which k of
// the current pair this lane processes. Loads are LDG.128. Two-stage register
// pipeline keeps 4 k's (2 pairs) in flight per warp.
// ---------------------------------------------------------------------------
__global__ void __launch_bounds__(128, 7) attn_kernel(const float* __restrict__ msg,
                                                      const int*   __restrict__ adjm,
                                                      const float* __restrict__ Wa,
                                                      float*       __restrict__ out) {
    __shared__ __align__(16) float Wt[64 * 65];      // Wt[e*65 + d] = Wa[d*64 + e]
    __shared__ __align__(16) float ao[12][64];       // [q_local*3 + c][e]
    __shared__ short klist[4][NKV + 8];

    int t = threadIdx.x;
    int w = t >> 5, l = t & 31;
    int li = l & 15, h = l >> 4;
    int b = blockIdx.x >> 6;
    int qbase = (blockIdx.x & 63) << 2;
    int q = qbase + w;

    for (int i = t; i < 4096; i += 128) {
        Wt[(i & 63) * 65 + (i >> 6)] = Wa[i];
    }

    // build mask + compact active-k list
    const int* arow = adjm + (b * NQ + q) * NKV;
    unsigned mask[8];
    unsigned any = 0u;
    #pragma unroll
    for (int c = 0; c < 8; c++) {
        mask[c] = __ballot_sync(0xffffffffu, arow[c * 32 + l] != 0);
        any |= mask[c];
    }
    if (!any) {
        #pragma unroll
        for (int c = 0; c < 8; c++) mask[c] = 0xffffffffu;
    }
    int cnt = 0;
    #pragma unroll
    for (int c = 0; c < 8; c++) {
        unsigned m = mask[c];
        if ((m >> l) & 1u) {
            klist[w][cnt + __popc(m & ((1u << l) - 1u))] = (short)(c * 32 + l);
        }
        cnt += __popc(m);
    }
    __syncwarp();
    if (l < 8) klist[w][cnt + l] = klist[w][cnt - 1];   // pad (cnt >= 1 always)
    __syncwarp();

    const float4* msg4  = (const float4*)msg + (size_t)(b * NQ + q) * (NKV * 16);
    const float4* proj4 = (const float4*)g_proj + (size_t)b * (NKV * 48);

    // accumulators: 4 d's per lane x 5 quantities
    float dn[4] = {0.f, 0.f, 0.f, 0.f};
    float w2[4] = {0.f, 0.f, 0.f, 0.f};
    float a0[4] = {0.f, 0.f, 0.f, 0.f};
    float a1[4] = {0.f, 0.f, 0.f, 0.f};
    float a2[4] = {0.f, 0.f, 0.f, 0.f};

    // prologue: pairs 0 and 1 into stages A, B
    int kA = klist[w][0 + h];
    int kB = klist[w][2 + h];
    float4 Am  = msg4[kA * 16 + li];
    float4 Ap0 = proj4[kA * 48 + li];
    float4 Ap1 = proj4[kA * 48 + 16 + li];
    float4 Ap2 = proj4[kA * 48 + 32 + li];
    float4 Bm  = msg4[kB * 16 + li];
    float4 Bp0 = proj4[kB * 48 + li];
    float4 Bp1 = proj4[kB * 48 + 16 + li];
    float4 Bp2 = proj4[kB * 48 + 32 + li];

    for (int j = 0; j < cnt; j += 4) {
        // ---- consume stage A (pair j), prefetch pair j+4 into A ----
        {
            float4 m = Am, p0 = Ap0, p1 = Ap1, p2 = Ap2;
            int kn = klist[w][j + 4 + h];
            Am  = msg4[kn * 16 + li];
            Ap0 = proj4[kn * 48 + li];
            Ap1 = proj4[kn * 48 + 16 + li];
            Ap2 = proj4[kn * 48 + 32 + li];

            float f = (j + h < cnt) ? 1.f : 0.f;
            float e0 = __expf(m.x) * f;
            float e1 = __expf(m.y) * f;
            float e2 = __expf(m.z) * f;
            float e3 = __expf(m.w) * f;
            dn[0] += e0; dn[1] += e1; dn[2] += e2; dn[3] += e3;
            w2[0] = fmaf(e0, e0, w2[0]); w2[1] = fmaf(e1, e1, w2[1]);
            w2[2] = fmaf(e2, e2, w2[2]); w2[3] = fmaf(e3, e3, w2[3]);
            a0[0] = fmaf(e0, p0.x, a0[0]); a0[1] = fmaf(e1, p0.y, a0[1]);
            a0[2] = fmaf(e2, p0.z, a0[2]); a0[3] = fmaf(e3, p0.w, a0[3]);
            a1[0] = fmaf(e0, p1.x, a1[0]); a1[1] = fmaf(e1, p1.y, a1[1]);
            a1[2] = fmaf(e2, p1.z, a1[2]); a1[3] = fmaf(e3, p1.w, a1[3]);
            a2[0] = fmaf(e0, p2.x, a2[0]); a2[1] = fmaf(e1, p2.y, a2[1]);
            a2[2] = fmaf(e2, p2.z, a2[2]); a2[3] = fmaf(e3, p2.w, a2[3]);
        }
        // ---- consume stage B (pair j+2), prefetch pair j+6 into B ----
        {
            float4 m = Bm, p0 = Bp0, p1 = Bp1, p2 = Bp2;
            int kn = klist[w][j + 6 + h];
            Bm  = msg4[kn * 16 + li];
            Bp0 = proj4[kn * 48 + li];
            Bp1 = proj4[kn * 48 + 16 + li];
            Bp2 = proj4[kn * 48 + 32 + li];

            float f = (j + 2 + h < cnt) ? 1.f : 0.f;
            float e0 = __expf(m.x) * f;
            float e1 = __expf(m.y) * f;
            float e2 = __expf(m.z) * f;
            float e3 = __expf(m.w) * f;
            dn[0] += e0; dn[1] += e1; dn[2] += e2; dn[3] += e3;
            w2[0] = fmaf(e0, e0, w2[0]); w2[1] = fmaf(e1, e1, w2[1]);
            w2[2] = fmaf(e2, e2, w2[2]); w2[3] = fmaf(e3, e3, w2[3]);
            a0[0] = fmaf(e0, p0.x, a0[0]); a0[1] = fmaf(e1, p0.y, a0[1]);
            a0[2] = fmaf(e2, p0.z, a0[2]); a0[3] = fmaf(e3, p0.w, a0[3]);
            a1[0] = fmaf(e0, p1.x, a1[0]); a1[1] = fmaf(e1, p1.y, a1[1]);
            a1[2] = fmaf(e2, p1.z, a1[2]); a1[3] = fmaf(e3, p1.w, a1[3]);
            a2[0] = fmaf(e0, p2.x, a2[0]); a2[1] = fmaf(e1, p2.y, a2[1]);
            a2[2] = fmaf(e2, p2.z, a2[2]); a2[3] = fmaf(e3, p2.w, a2[3]);
        }
    }

    // combine the two half-warp k-partitions
    #pragma unroll
    for (int i = 0; i < 4; i++) {
        dn[i] += __shfl_down_sync(0xffffffffu, dn[i], 16);
        w2[i] += __shfl_down_sync(0xffffffffu, w2[i], 16);
        a0[i] += __shfl_down_sync(0xffffffffu, a0[i], 16);
        a1[i] += __shfl_down_sync(0xffffffffu, a1[i], 16);
        a2[i] += __shfl_down_sync(0xffffffffu, a2[i], 16);
    }

    if (h == 0) {
        // attn_out = acc * sqrt(w2) / den^2
        #pragma unroll
        for (int i = 0; i < 4; i++) {
            float s = sqrtf(w2[i]) / (dn[i] * dn[i]);
            ao[w * 3 + 0][li * 4 + i] = a0[i] * s;
            ao[w * 3 + 1][li * 4 + i] = a1[i] * s;
            ao[w * 3 + 2][li * 4 + i] = a2[i] * s;
        }
    }
    __syncthreads();

    // epilogue: out[(q,c),d] = sum_e ao[(q,c)][e] * Wa[d][e]
    int d = t & 63;
    int half = t >> 6;
    float acc[6];
    const float* aop[6];
    #pragma unroll
    for (int jj = 0; jj < 6; jj++) {
        acc[jj] = 0.f;
        aop[jj] = &ao[0][0] + (half + 2 * jj) * 64;
    }
    #pragma unroll 4
    for (int e = 0; e < 64; e++) {
        float wt = Wt[e * 65 + d];
        #pragma unroll
        for (int jj = 0; jj < 6; jj++) {
            acc[jj] = fmaf(aop[jj][e], wt, acc[jj]);
        }
    }
    float* orow = out + ((size_t)(b * NQ + qbase) * 3) * 64;
    #pragma unroll
    for (int jj = 0; jj < 6; jj++) {
        int r = half + 2 * jj;          // r = q_local*3 + c
        orow[r * 64 + d] = acc[jj];
    }
}

extern "C" void kernel_launch(void* const* d_in, const int* in_sizes, int n_in,
                              void* d_out, int out_size) {
    const float* v_equi   = (const float*)d_in[0];
    const float* messages = (const float*)d_in[1];
    const int*   adj_mask = (const int*)d_in[2];
    const float* W_coord  = (const float*)d_in[3];
    const float* W_attn   = (const float*)d_in[4];
    float* out = (float*)d_out;

    proj_kernel<<<296, 128>>>(v_equi, W_coord);
    attn_kernel<<<BB * (NQ / 4), 128>>>(messages, adj_mask, W_attn, out);
}